// round 9
// baseline (speedup 1.0000x reference)
#include <cuda_runtime.h>
#include <cuda_fp16.h>
#include <cstdint>

#define B_SZ  4096
#define IN_F  256
#define OUT_F 256
#define HYP   128
#define BM    128
#define BN    64

// ---------------- device scratch (allocation-free rule) ----------------
__device__ __align__(256) float  g_hgT[HYP * B_SZ];                    // [h][b] fp32
__device__ __align__(256) __half g_hb16[B_SZ * HYP];                   // [b][h]
__device__ __align__(256) __half g_x16[B_SZ * IN_F];                   // [b][i]
__device__ __align__(256) __half g_w2g16[(size_t)HYP * OUT_F * IN_F];  // [h][o][i]
__device__ __align__(256) __half g_b2g16[OUT_F * IN_F];                // [o][i]
__device__ __align__(256) __half g_w2bT16[OUT_F * HYP];                // [o][k]

// ---------------- PTX helpers (sm_80+ baseline ISA only) ----------------
__device__ __forceinline__ uint32_t smem_u32(const void* p) {
    uint32_t a;
    asm("{ .reg .u64 t; cvta.to.shared.u64 t, %1; cvt.u32.u64 %0, t; }" : "=r"(a) : "l"(p));
    return a;
}
#define CP16(dst, src) \
    asm volatile("cp.async.cg.shared.global [%0], [%1], 16;" :: "r"(dst), "l"(src) : "memory")
#define CP_COMMIT() asm volatile("cp.async.commit_group;" ::: "memory")
#define CP_WAIT(n)  asm volatile("cp.async.wait_group %0;" :: "n"(n) : "memory")

__device__ __forceinline__ void ldsm4(uint32_t* r, uint32_t addr) {
    asm volatile("ldmatrix.sync.aligned.m8n8.x4.shared.b16 {%0,%1,%2,%3}, [%4];"
        : "=r"(r[0]), "=r"(r[1]), "=r"(r[2]), "=r"(r[3]) : "r"(addr));
}
// d += A(16x16) * B(16x8)
__device__ __forceinline__ void mma_16816(float* d, const uint32_t* a, const uint32_t* b) {
    asm volatile(
        "mma.sync.aligned.m16n8k16.row.col.f32.f16.f16.f32 "
        "{%0,%1,%2,%3}, {%4,%5,%6,%7}, {%8,%9}, {%0,%1,%2,%3};"
        : "+f"(d[0]), "+f"(d[1]), "+f"(d[2]), "+f"(d[3])
        : "r"(a[0]), "r"(a[1]), "r"(a[2]), "r"(a[3]), "r"(b[0]), "r"(b[1]));
}
// d = A(16x16) * B(16x8)   (no accumulate: C = 0)
__device__ __forceinline__ void mma_16816_init(float* d, const uint32_t* a, const uint32_t* b) {
    asm volatile(
        "mma.sync.aligned.m16n8k16.row.col.f32.f16.f16.f32 "
        "{%0,%1,%2,%3}, {%4,%5,%6,%7}, {%8,%9}, {%10,%10,%10,%10};"
        : "=f"(d[0]), "=f"(d[1]), "=f"(d[2]), "=f"(d[3])
        : "r"(a[0]), "r"(a[1]), "r"(a[2]), "r"(a[3]), "r"(b[0]), "r"(b[1]), "f"(0.f));
}

// ---------------- kernel 0: prep = convert (blocks 256..1023) + hidden (blocks 0..255)
__global__ __launch_bounds__(256) void prep_kernel(
    const float* __restrict__ x,
    const float* __restrict__ W1g, const float* __restrict__ b1g,
    const float* __restrict__ W1b, const float* __restrict__ b1b,
    const float* __restrict__ W2g, const float* __restrict__ b2g,
    const float* __restrict__ W2b)
{
    if (blockIdx.x < 256) {
        __shared__ __align__(16) float xs[16 * IN_F];
        const int b0 = blockIdx.x * 16;
        const int tid = threadIdx.x;
        const int h = tid & (HYP - 1);
        const int half = tid >> 7;

        for (int idx = tid; idx < 16 * IN_F / 4; idx += 256)
            ((float4*)xs)[idx] = ((const float4*)(x + (size_t)b0 * IN_F))[idx];
        __syncthreads();

        float accg[8], accb[8];
#pragma unroll
        for (int r = 0; r < 8; r++) { accg[r] = 0.f; accb[r] = 0.f; }
        for (int i = 0; i < IN_F; i++) {
            float wg = W1g[i * HYP + h];
            float wb = W1b[i * HYP + h];
#pragma unroll
            for (int r = 0; r < 8; r++) {
                float xv = xs[(half * 8 + r) * IN_F + i];
                accg[r] = fmaf(xv, wg, accg[r]);
                accb[r] = fmaf(xv, wb, accb[r]);
            }
        }
        float bg = b1g[h], bb = b1b[h];
#pragma unroll
        for (int r = 0; r < 8; r++) {
            int row = b0 + half * 8 + r;
            g_hgT[(size_t)h * B_SZ + row] = fmaxf(accg[r] + bg, 0.f);
            g_hb16[(size_t)row * HYP + h] = __float2half_rn(fmaxf(accb[r] + bb, 0.f));
        }
    } else {
        int64_t tid = (int64_t)(blockIdx.x - 256) * 256 + threadIdx.x;
        if (tid < OUT_F * HYP) {
            int o = (int)(tid >> 7), k = (int)(tid & 127);
            g_w2bT16[tid] = __float2half_rn(W2b[k * OUT_F + o]);
        }
        const int64_t N1 = (int64_t)HYP * OUT_F * IN_F / 4;
        const int64_t N2 = N1 + (int64_t)OUT_F * IN_F / 4;
        const int64_t N3 = N2 + (int64_t)B_SZ * IN_F / 4;
        const int64_t stride = (int64_t)768 * 256;
        for (int64_t i = tid; i < N3; i += stride) {
            const float4* src; __half* dst; int64_t j;
            if (i < N1)      { src = (const float4*)W2g; dst = g_w2g16; j = i; }
            else if (i < N2) { src = (const float4*)b2g; dst = g_b2g16; j = i - N1; }
            else             { src = (const float4*)x;   dst = g_x16;   j = i - N2; }
            float4 v = src[j];
            __half2* d2 = (__half2*)(dst + j * 4);
            d2[0] = __floats2half2_rn(v.x, v.y);
            d2[1] = __floats2half2_rn(v.z, v.w);
        }
    }
}

// ---------------- kernel 1: mma.sync main, 512 threads, warp-level k-split ----
// smem: X 128x512B swizzled (64KB) | HB 128x256B swizzled (32KB)
//       B 3x 64x512B (96KB; tail-reused as 32KB reduce buffer) | S 4x 512B
#define X_OFF   0
#define HB_OFF  65536
#define B_OFF   98304
#define S_OFF   196608
#define SMEM_TOTAL 198656
#define NT 512

__global__ __launch_bounds__(NT, 1) void main_kernel(
    float* __restrict__ out, const float* __restrict__ b2b)
{
    extern __shared__ __align__(1024) char smem[];
    const uint32_t sb = smem_u32(smem);
    const int tid = threadIdx.x;
    const int lane = tid & 31;
    const int wid = tid >> 5;       // 0..15
    const int wlo = wid & 7;        // tile position
    const int khalf = wid >> 3;     // 0: k[0,128), 1: k[128,256)
    const int wm = wlo & 3;         // warp M position (x32)
    const int wn = wlo >> 2;        // warp N position (x32)
    const int b0 = blockIdx.x * BM;
    const int o0 = blockIdx.y * BN;

    // B-tile (buffer hh%3) + hg scale (buffer hh&3) prefetch; one commit group always
    auto issueB = [&](int hh) {
        if (hh <= 129) {
            uint32_t dbuf = sb + B_OFF + (uint32_t)(hh % 3) * 32768;
            const __half* src; int nsh;
            if (hh < 128)       { src = g_w2g16 + (size_t)hh * OUT_F * IN_F + (size_t)o0 * IN_F; nsh = 5; }
            else if (hh == 128) { src = g_b2g16 + (size_t)o0 * IN_F; nsh = 5; }
            else                { src = g_w2bT16 + (size_t)o0 * HYP; nsh = 4; }
            int ldh = 1 << (nsh + 3);
            int msk = (1 << nsh) - 1;
            int tot = 64 << nsh;
            for (int idx = tid; idx < tot; idx += NT) {
                int row = idx >> nsh, k8 = idx & msk;
                CP16(dbuf + row * 512 + (uint32_t)((k8 ^ (row & 7)) << 4),
                     src + (size_t)row * ldh + k8 * 8);
            }
            if (hh < 128 && tid < 32)
                CP16(sb + S_OFF + (uint32_t)(hh & 3) * 512 + tid * 16,
                     g_hgT + (size_t)hh * B_SZ + b0 + tid * 4);
        }
        CP_COMMIT();
    };

    // ---- prologue: g0 = X + HB; g1 = B0 + S0; g2 = B1 + S1 ----
    for (int idx = tid; idx < 128 * 32; idx += NT) {
        int row = idx >> 5, k8 = idx & 31;
        CP16(sb + X_OFF + row * 512 + (uint32_t)((k8 ^ (row & 7)) << 4),
             g_x16 + (size_t)(b0 + row) * IN_F + k8 * 8);
    }
    for (int idx = tid; idx < 128 * 16; idx += NT) {
        int row = idx >> 4, k8 = idx & 15;
        CP16(sb + HB_OFF + row * 256 + (uint32_t)((k8 ^ (row & 7)) << 4),
             g_hb16 + (size_t)(b0 + row) * HYP + k8 * 8);
    }
    CP_COMMIT();
    issueB(0);
    issueB(1);

    // ---- per-thread fragment addressing ----
    const uint32_t a_row = (uint32_t)(wm * 32 + (lane & 15));
    const uint32_t a_sw  = (uint32_t)(lane & 7);
    const uint32_t a_hi  = (uint32_t)(lane >> 4);
    uint32_t b_off[4];
#pragma unroll
    for (int nn = 0; nn < 4; nn++)
        b_off[nn] = (uint32_t)(wn * 32 + nn * 8 + (lane & 7)) * 512;
    const uint32_t b_sw = (uint32_t)(lane & 7);
    const uint32_t b_hi = (uint32_t)(lane >> 3);

    float c[2][4][4];
    float p[2][4][4];
#pragma unroll
    for (int mf = 0; mf < 2; mf++)
#pragma unroll
        for (int nn = 0; nn < 4; nn++)
#pragma unroll
            for (int e = 0; e < 4; e++) c[mf][nn][e] = 0.f;

    const uint32_t xb  = sb + X_OFF;
    const uint32_t hbb = sb + HB_OFF;

    // one h iteration: this warp covers k32 range [khalf*nh, khalf*nh+nh)
    auto run_h = [&](int h, uint32_t abase, uint32_t rs, int nh) {
        CP_WAIT(1);
        __syncthreads();
        issueB(h + 2);
        const uint32_t bbase = sb + B_OFF + (uint32_t)(h % 3) * 32768;
        const int k0 = khalf * nh;

        float s2[4] = {1.f, 1.f, 1.f, 1.f};
        if (h < 128) {
            const float* ss = (const float*)(smem + S_OFF + (size_t)(h & 3) * 512);
#pragma unroll
            for (int mf = 0; mf < 2; mf++)
#pragma unroll
                for (int g = 0; g < 2; g++)
                    s2[mf * 2 + g] = ss[wm * 32 + mf * 16 + g * 8 + (lane >> 2)];
        }

#pragma unroll
        for (int j = 0; j < 4; j++) {
            if (j >= nh) break;
            const int k32 = k0 + j;
            uint32_t Af[2][2][4];
#pragma unroll
            for (int mf = 0; mf < 2; mf++)
#pragma unroll
                for (int kr = 0; kr < 2; kr++) {
                    uint32_t k8 = (uint32_t)(k32 * 4 + kr * 2) + a_hi;
                    ldsm4(Af[mf][kr],
                          abase + (a_row + (uint32_t)mf * 16) * rs + ((k8 ^ a_sw) << 4));
                }
            uint32_t Bf[4][4];
#pragma unroll
            for (int nn = 0; nn < 4; nn++) {
                uint32_t k8 = (uint32_t)(k32 * 4) + b_hi;
                ldsm4(Bf[nn], bbase + b_off[nn] + ((k8 ^ b_sw) << 4));
            }
#pragma unroll
            for (int kr = 0; kr < 2; kr++)
#pragma unroll
                for (int mf = 0; mf < 2; mf++)
#pragma unroll
                    for (int nn = 0; nn < 4; nn++) {
                        if (j == 0 && kr == 0)
                            mma_16816_init(p[mf][nn], Af[mf][0], &Bf[nn][0]);
                        else
                            mma_16816(p[mf][nn], Af[mf][kr], &Bf[nn][kr * 2]);
                    }
        }

#pragma unroll
        for (int mf = 0; mf < 2; mf++)
#pragma unroll
            for (int nn = 0; nn < 4; nn++)
#pragma unroll
                for (int e = 0; e < 4; e++)
                    c[mf][nn][e] = fmaf(s2[mf * 2 + (e >> 1)], p[mf][nn][e], c[mf][nn][e]);
    };

    // ---- mainloop: h<128 W2g[h] (scaled); 128 b2g (s=1); 129 hb@W2bT (s=1) ----
#pragma unroll 1
    for (int h = 0; h < 129; h++)
        run_h(h, xb, 512u, 4);
    run_h(129, hbb, 256u, 2);

    // ---- cross-half reduction through smem (reuse B region; cp.async drained) ----
    CP_WAIT(0);
    __syncthreads();
    float* red = (float*)(smem + B_OFF);   // [32][256]: idx-major, lane-contiguous
    if (khalf == 1) {
#pragma unroll
        for (int mf = 0; mf < 2; mf++)
#pragma unroll
            for (int nn = 0; nn < 4; nn++)
#pragma unroll
                for (int e = 0; e < 4; e++)
                    red[(mf * 16 + nn * 4 + e) * 256 + wlo * 32 + lane] = c[mf][nn][e];
    }
    __syncthreads();
    if (khalf == 0) {
        const int r_base = b0 + wm * 32 + (lane >> 2);
        const int c_base = o0 + wn * 32 + (lane & 3) * 2;
#pragma unroll
        for (int mf = 0; mf < 2; mf++)
#pragma unroll
            for (int nn = 0; nn < 4; nn++) {
                float2 bb2 = *(const float2*)(b2b + c_base + nn * 8);
                float v4[4];
#pragma unroll
                for (int e = 0; e < 4; e++)
                    v4[e] = c[mf][nn][e] + red[(mf * 16 + nn * 4 + e) * 256 + wlo * 32 + lane];
#pragma unroll
                for (int g = 0; g < 2; g++) {
                    int row = r_base + mf * 16 + g * 8;
                    float2 v;
                    v.x = v4[g * 2 + 0] + bb2.x;
                    v.y = v4[g * 2 + 1] + bb2.y;
                    *(float2*)(out + (size_t)row * OUT_F + c_base + nn * 8) = v;
                }
            }
    }
}

// ---------------- launch ----------------
extern "C" void kernel_launch(void* const* d_in, const int* in_sizes, int n_in,
                              void* d_out, int out_size)
{
    const float* x   = (const float*)d_in[0];
    const float* W1g = (const float*)d_in[1];
    const float* b1g = (const float*)d_in[2];
    const float* W2g = (const float*)d_in[3];
    const float* b2g = (const float*)d_in[4];
    const float* W1b = (const float*)d_in[5];
    const float* b1b = (const float*)d_in[6];
    const float* W2b = (const float*)d_in[7];
    const float* b2b = (const float*)d_in[8];
    float* out = (float*)d_out;

    cudaFuncSetAttribute(main_kernel, cudaFuncAttributeMaxDynamicSharedMemorySize, SMEM_TOTAL);

    prep_kernel<<<1024, 256>>>(x, W1g, b1g, W1b, b1b, W2g, b2g, W2b);
    dim3 grid(B_SZ / BM, OUT_F / BN);
    main_kernel<<<grid, 512, SMEM_TOTAL>>>(out, b2b);
}

// round 10
// speedup vs baseline: 1.0625x; 1.0625x over previous
#include <cuda_runtime.h>
#include <cuda_fp16.h>
#include <cstdint>

#define B_SZ  4096
#define IN_F  256
#define OUT_F 256
#define HYP   128
#define BM    128
#define BN    64

// ---------------- device scratch (allocation-free rule) ----------------
__device__ __align__(256) float  g_hgT[HYP * B_SZ];                    // [h][b] fp32
__device__ __align__(256) __half g_hb16[B_SZ * HYP];                   // [b][h]
__device__ __align__(256) __half g_x16[B_SZ * IN_F];                   // [b][i]
__device__ __align__(256) __half g_w2g16[(size_t)HYP * OUT_F * IN_F];  // [h][o][i]
__device__ __align__(256) __half g_b2g16[OUT_F * IN_F];                // [o][i]
__device__ __align__(256) __half g_w2bT16[OUT_F * HYP];                // [o][k]
__device__ __align__(256) float  g_partA[B_SZ * OUT_F];                // k-half 0 partial
__device__ __align__(256) float  g_partB[B_SZ * OUT_F];                // k-half 1 partial

// ---------------- PTX helpers (sm_80+ baseline ISA only) ----------------
__device__ __forceinline__ uint32_t smem_u32(const void* p) {
    uint32_t a;
    asm("{ .reg .u64 t; cvta.to.shared.u64 t, %1; cvt.u32.u64 %0, t; }" : "=r"(a) : "l"(p));
    return a;
}
#define CP16(dst, src) \
    asm volatile("cp.async.cg.shared.global [%0], [%1], 16;" :: "r"(dst), "l"(src) : "memory")
#define CP_COMMIT() asm volatile("cp.async.commit_group;" ::: "memory")
#define CP_WAIT(n)  asm volatile("cp.async.wait_group %0;" :: "n"(n) : "memory")

__device__ __forceinline__ void ldsm4(uint32_t* r, uint32_t addr) {
    asm volatile("ldmatrix.sync.aligned.m8n8.x4.shared.b16 {%0,%1,%2,%3}, [%4];"
        : "=r"(r[0]), "=r"(r[1]), "=r"(r[2]), "=r"(r[3]) : "r"(addr));
}
// d += A(16x16) * B(16x8)
__device__ __forceinline__ void mma_16816(float* d, const uint32_t* a, const uint32_t* b) {
    asm volatile(
        "mma.sync.aligned.m16n8k16.row.col.f32.f16.f16.f32 "
        "{%0,%1,%2,%3}, {%4,%5,%6,%7}, {%8,%9}, {%0,%1,%2,%3};"
        : "+f"(d[0]), "+f"(d[1]), "+f"(d[2]), "+f"(d[3])
        : "r"(a[0]), "r"(a[1]), "r"(a[2]), "r"(a[3]), "r"(b[0]), "r"(b[1]));
}
// d = A(16x16) * B(16x8)   (no accumulate: C = 0)
__device__ __forceinline__ void mma_16816_init(float* d, const uint32_t* a, const uint32_t* b) {
    asm volatile(
        "mma.sync.aligned.m16n8k16.row.col.f32.f16.f16.f32 "
        "{%0,%1,%2,%3}, {%4,%5,%6,%7}, {%8,%9}, {%10,%10,%10,%10};"
        : "=f"(d[0]), "=f"(d[1]), "=f"(d[2]), "=f"(d[3])
        : "r"(a[0]), "r"(a[1]), "r"(a[2]), "r"(a[3]), "r"(b[0]), "r"(b[1]), "f"(0.f));
}

// ---------------- kernel 0: prep = convert (blocks 256..1023) + hidden (blocks 0..255)
__global__ __launch_bounds__(256) void prep_kernel(
    const float* __restrict__ x,
    const float* __restrict__ W1g, const float* __restrict__ b1g,
    const float* __restrict__ W1b, const float* __restrict__ b1b,
    const float* __restrict__ W2g, const float* __restrict__ b2g,
    const float* __restrict__ W2b)
{
    if (blockIdx.x < 256) {
        __shared__ __align__(16) float xs[16 * IN_F];
        const int b0 = blockIdx.x * 16;
        const int tid = threadIdx.x;
        const int h = tid & (HYP - 1);
        const int half = tid >> 7;

        for (int idx = tid; idx < 16 * IN_F / 4; idx += 256)
            ((float4*)xs)[idx] = ((const float4*)(x + (size_t)b0 * IN_F))[idx];
        __syncthreads();

        float accg[8], accb[8];
#pragma unroll
        for (int r = 0; r < 8; r++) { accg[r] = 0.f; accb[r] = 0.f; }
        for (int i = 0; i < IN_F; i++) {
            float wg = W1g[i * HYP + h];
            float wb = W1b[i * HYP + h];
#pragma unroll
            for (int r = 0; r < 8; r++) {
                float xv = xs[(half * 8 + r) * IN_F + i];
                accg[r] = fmaf(xv, wg, accg[r]);
                accb[r] = fmaf(xv, wb, accb[r]);
            }
        }
        float bg = b1g[h], bb = b1b[h];
#pragma unroll
        for (int r = 0; r < 8; r++) {
            int row = b0 + half * 8 + r;
            g_hgT[(size_t)h * B_SZ + row] = fmaxf(accg[r] + bg, 0.f);
            g_hb16[(size_t)row * HYP + h] = __float2half_rn(fmaxf(accb[r] + bb, 0.f));
        }
    } else {
        int64_t tid = (int64_t)(blockIdx.x - 256) * 256 + threadIdx.x;
        if (tid < OUT_F * HYP) {
            int o = (int)(tid >> 7), k = (int)(tid & 127);
            g_w2bT16[tid] = __float2half_rn(W2b[k * OUT_F + o]);
        }
        const int64_t N1 = (int64_t)HYP * OUT_F * IN_F / 4;
        const int64_t N2 = N1 + (int64_t)OUT_F * IN_F / 4;
        const int64_t N3 = N2 + (int64_t)B_SZ * IN_F / 4;
        const int64_t stride = (int64_t)768 * 256;
        for (int64_t i = tid; i < N3; i += stride) {
            const float4* src; __half* dst; int64_t j;
            if (i < N1)      { src = (const float4*)W2g; dst = g_w2g16; j = i; }
            else if (i < N2) { src = (const float4*)b2g; dst = g_b2g16; j = i - N1; }
            else             { src = (const float4*)x;   dst = g_x16;   j = i - N2; }
            float4 v = src[j];
            __half2* d2 = (__half2*)(dst + j * 4);
            d2[0] = __floats2half2_rn(v.x, v.y);
            d2[1] = __floats2half2_rn(v.z, v.w);
        }
    }
}

// ---------------- kernel 1: mma.sync main, k-split across 2 CTAs/SM ----------
// Each CTA owns k-half khalf*128..+128.  smem per CTA (98KB):
//   X 128x256B swz (32KB) | HB 128x128B swz (16KB) | B 3x 64x256B (48KB) | S 4x512B
#define X_OFF   0
#define HB_OFF  32768
#define B_OFF   49152
#define S_OFF   98304
#define SMEM_TOTAL 100352

__global__ __launch_bounds__(256, 2) void main_kernel(const float* __restrict__ dummy)
{
    extern __shared__ __align__(1024) char smem[];
    const uint32_t sb = smem_u32(smem);
    const int tid = threadIdx.x;
    const int lane = tid & 31;
    const int wid = tid >> 5;       // 0..7
    const int wm = wid & 3;         // warp M position (x32)
    const int wn = wid >> 2;        // warp N position (x32)
    const int b0 = blockIdx.x * BM;
    const int o0 = blockIdx.y * BN;
    const int khalf = blockIdx.z;   // 0 or 1
    const int koffI = khalf * 128;  // halves offset in IN_F-strided rows
    const int koffH = khalf * 64;   // halves offset in HYP-strided rows

    // B-tile (buffer hh%3) + hg scale (buffer hh&3) prefetch; one commit group always
    auto issueB = [&](int hh) {
        if (hh <= 129) {
            uint32_t dbuf = sb + B_OFF + (uint32_t)(hh % 3) * 16384;
            const __half* src; int nsh, srow;
            if (hh < 128)       { src = g_w2g16 + (size_t)hh * OUT_F * IN_F + (size_t)o0 * IN_F + koffI; nsh = 4; srow = IN_F; }
            else if (hh == 128) { src = g_b2g16 + (size_t)o0 * IN_F + koffI; nsh = 4; srow = IN_F; }
            else                { src = g_w2bT16 + (size_t)o0 * HYP + koffH; nsh = 3; srow = HYP; }
            const int rowb = 16 << nsh;
            const int msk = (1 << nsh) - 1;
            const int tot = 64 << nsh;
            for (int idx = tid; idx < tot; idx += 256) {
                int row = idx >> nsh, k8 = idx & msk;
                CP16(dbuf + row * rowb + (uint32_t)((k8 ^ (row & 7)) << 4),
                     src + (size_t)row * srow + k8 * 8);
            }
            if (hh < 128 && tid < 32)
                CP16(sb + S_OFF + (uint32_t)(hh & 3) * 512 + tid * 16,
                     g_hgT + (size_t)hh * B_SZ + b0 + tid * 4);
        }
        CP_COMMIT();
    };

    // ---- prologue: g0 = X + HB; g1 = B0 + S0; g2 = B1 + S1 ----
    for (int idx = tid; idx < 128 * 16; idx += 256) {
        int row = idx >> 4, k8 = idx & 15;
        CP16(sb + X_OFF + row * 256 + (uint32_t)((k8 ^ (row & 7)) << 4),
             g_x16 + (size_t)(b0 + row) * IN_F + koffI + k8 * 8);
    }
    for (int idx = tid; idx < 128 * 8; idx += 256) {
        int row = idx >> 3, k8 = idx & 7;
        CP16(sb + HB_OFF + row * 128 + (uint32_t)((k8 ^ (row & 7)) << 4),
             g_hb16 + (size_t)(b0 + row) * HYP + koffH + k8 * 8);
    }
    CP_COMMIT();
    issueB(0);
    issueB(1);

    // ---- per-thread fragment addressing ----
    const uint32_t a_row = (uint32_t)(wm * 32 + (lane & 15));
    const uint32_t a_sw  = (uint32_t)(lane & 7);
    const uint32_t a_hi  = (uint32_t)(lane >> 4);
    const uint32_t b_row = (uint32_t)(wn * 32 + (lane & 7));   // +nn*8 applied per-frag
    const uint32_t b_sw  = (uint32_t)(lane & 7);
    const uint32_t b_hi  = (uint32_t)(lane >> 3);

    float c[2][4][4];
    float p[2][4][4];
#pragma unroll
    for (int mf = 0; mf < 2; mf++)
#pragma unroll
        for (int nn = 0; nn < 4; nn++)
#pragma unroll
            for (int e = 0; e < 4; e++) c[mf][nn][e] = 0.f;

    // one h iteration: nk k32-steps over this CTA's k-half
    auto run_h = [&](int h, uint32_t abase, uint32_t ars, uint32_t brs, int nk) {
        CP_WAIT(1);
        __syncthreads();
        issueB(h + 2);
        const uint32_t bbase = sb + B_OFF + (uint32_t)(h % 3) * 16384;

        float s2[4] = {1.f, 1.f, 1.f, 1.f};
        if (h < 128) {
            const float* ss = (const float*)(smem + S_OFF + (size_t)(h & 3) * 512);
#pragma unroll
            for (int mf = 0; mf < 2; mf++)
#pragma unroll
                for (int g = 0; g < 2; g++)
                    s2[mf * 2 + g] = ss[wm * 32 + mf * 16 + g * 8 + (lane >> 2)];
        }

#pragma unroll
        for (int j = 0; j < 4; j++) {
            if (j >= nk) break;
            uint32_t Af[2][2][4];
#pragma unroll
            for (int mf = 0; mf < 2; mf++)
#pragma unroll
                for (int kr = 0; kr < 2; kr++) {
                    uint32_t k8 = (uint32_t)(j * 4 + kr * 2) + a_hi;
                    ldsm4(Af[mf][kr],
                          abase + (a_row + (uint32_t)mf * 16) * ars + ((k8 ^ a_sw) << 4));
                }
            uint32_t Bf[4][4];
#pragma unroll
            for (int nn = 0; nn < 4; nn++) {
                uint32_t k8 = (uint32_t)(j * 4) + b_hi;
                ldsm4(Bf[nn], bbase + (b_row + (uint32_t)nn * 8) * brs + ((k8 ^ b_sw) << 4));
            }
#pragma unroll
            for (int kr = 0; kr < 2; kr++)
#pragma unroll
                for (int mf = 0; mf < 2; mf++)
#pragma unroll
                    for (int nn = 0; nn < 4; nn++) {
                        if (j == 0 && kr == 0)
                            mma_16816_init(p[mf][nn], Af[mf][0], &Bf[nn][0]);
                        else
                            mma_16816(p[mf][nn], Af[mf][kr], &Bf[nn][kr * 2]);
                    }
        }

#pragma unroll
        for (int mf = 0; mf < 2; mf++)
#pragma unroll
            for (int nn = 0; nn < 4; nn++)
#pragma unroll
                for (int e = 0; e < 4; e++)
                    c[mf][nn][e] = fmaf(s2[mf * 2 + (e >> 1)], p[mf][nn][e], c[mf][nn][e]);
    };

    // ---- mainloop: h<128 W2g[h] (scaled); 128 b2g (s=1); 129 hb@W2bT (s=1) ----
#pragma unroll 1
    for (int h = 0; h < 129; h++)
        run_h(h, sb + X_OFF, 256u, 256u, 4);
    run_h(129, sb + HB_OFF, 128u, 128u, 2);

    // ---- store partial (no bias; reduce kernel adds halves + b2b) ----
    float* part = (khalf == 0) ? g_partA : g_partB;
    const int r_base = b0 + wm * 32 + (lane >> 2);
    const int c_base = o0 + wn * 32 + (lane & 3) * 2;
#pragma unroll
    for (int mf = 0; mf < 2; mf++)
#pragma unroll
        for (int nn = 0; nn < 4; nn++)
#pragma unroll
            for (int g = 0; g < 2; g++) {
                int row = r_base + mf * 16 + g * 8;
                float2 v;
                v.x = c[mf][nn][g * 2 + 0];
                v.y = c[mf][nn][g * 2 + 1];
                *(float2*)(part + (size_t)row * OUT_F + c_base + nn * 8) = v;
            }
    (void)dummy;
}

// ---------------- kernel 2: out = partA + partB + b2b ----------------
__global__ __launch_bounds__(256) void reduce_kernel(
    float* __restrict__ out, const float* __restrict__ b2b)
{
    int idx = blockIdx.x * 256 + threadIdx.x;          // 1024 blocks -> 256K float4
    float4 a = ((const float4*)g_partA)[idx];
    float4 b = ((const float4*)g_partB)[idx];
    float4 bb = *(const float4*)(b2b + (idx & 63) * 4);
    float4 v;
    v.x = a.x + b.x + bb.x;
    v.y = a.y + b.y + bb.y;
    v.z = a.z + b.z + bb.z;
    v.w = a.w + b.w + bb.w;
    ((float4*)out)[idx] = v;
}

// ---------------- launch ----------------
extern "C" void kernel_launch(void* const* d_in, const int* in_sizes, int n_in,
                              void* d_out, int out_size)
{
    const float* x   = (const float*)d_in[0];
    const float* W1g = (const float*)d_in[1];
    const float* b1g = (const float*)d_in[2];
    const float* W2g = (const float*)d_in[3];
    const float* b2g = (const float*)d_in[4];
    const float* W1b = (const float*)d_in[5];
    const float* b1b = (const float*)d_in[6];
    const float* W2b = (const float*)d_in[7];
    const float* b2b = (const float*)d_in[8];
    float* out = (float*)d_out;

    cudaFuncSetAttribute(main_kernel, cudaFuncAttributeMaxDynamicSharedMemorySize, SMEM_TOTAL);

    prep_kernel<<<1024, 256>>>(x, W1g, b1g, W1b, b1b, W2g, b2g, W2b);
    dim3 grid(B_SZ / BM, OUT_F / BN, 2);
    main_kernel<<<grid, 256, SMEM_TOTAL>>>(x);
    reduce_kernel<<<B_SZ * OUT_F / 1024, 256>>>(out, b2b);
}